// round 15
// baseline (speedup 1.0000x reference)
#include <cuda_runtime.h>
#include <cuda_fp16.h>
#include <cstdint>

#define IDIM    256
#define HDIM    512
#define ODIM    10
#define BATCH   64
#define TSTEPS  2048
#define GB      128         // grid blocks (all co-resident; <=148 SMs)
#define NTH     256         // 8 warps
#define NHC     8           // h columns owned per n-group
#define NCTR    8           // barrier counters per step
#define CSTRIDE 64          // uint stride between counters (256 B -> distinct LTS)
#define ARRV    (GB / NCTR) // arrivals per counter (16)

// persistent device state (static __device__ is the sanctioned scratch path)
__device__ __half       g_h[2][BATCH][HDIM];            // double-buffered hidden state
__device__ __half       g_x[BATCH][TSTEPS][IDIM];       // fp16 copy of x (converted once)
__device__ unsigned int g_bar[TSTEPS][NCTR * CSTRIDE];  // hierarchical arrival counters

__device__ __forceinline__ uint32_t h2u(__half2 v) {
    uint32_t r;
    __builtin_memcpy(&r, &v, sizeof(r));
    return r;
}

__device__ __forceinline__ void mma_f16(float c[4],
                                        uint32_t a0, uint32_t a1, uint32_t a2, uint32_t a3,
                                        uint32_t b0, uint32_t b1) {
    asm("mma.sync.aligned.m16n8k16.row.col.f32.f16.f16.f32 "
        "{%0,%1,%2,%3}, {%4,%5,%6,%7}, {%8,%9}, {%0,%1,%2,%3};"
        : "+f"(c[0]), "+f"(c[1]), "+f"(c[2]), "+f"(c[3])
        : "r"(a0), "r"(a1), "r"(a2), "r"(a3), "r"(b0), "r"(b1));
}

__device__ __forceinline__ float sigf(float x)  { return 1.f / (1.f + __expf(-x)); }
__device__ __forceinline__ float tanhff(float x){ return 1.f - 2.f / (__expf(2.f * x) + 1.f); }

__global__ void init_kernel() {
    int idx = blockIdx.x * blockDim.x + threadIdx.x;
    int stride = gridDim.x * blockDim.x;
    __half* h = &g_h[0][0][0];
    for (int i = idx; i < 2 * BATCH * HDIM; i += stride) h[i] = __float2half(0.f);
    unsigned int* b = &g_bar[0][0];
    for (int i = idx; i < TSTEPS * NCTR * CSTRIDE; i += stride) b[i] = 0u;
}

// one-time fp32 -> fp16 conversion of x (8 floats / thread-iter)
__global__ void convert_x_kernel(const float* __restrict__ x) {
    const int N8 = BATCH * TSTEPS * IDIM / 8;
    uint2* dst = (uint2*)&g_x[0][0][0];
    int idx = blockIdx.x * blockDim.x + threadIdx.x;
    int stride = gridDim.x * blockDim.x;
    for (int i = idx; i < N8; i += stride) {
        float4 v0 = __ldcg((const float4*)x + 2 * i);
        float4 v1 = __ldcg((const float4*)x + 2 * i + 1);
        uint2 o;
        o.x = h2u(__floats2half2_rn(v0.x, v0.y));
        o.y = h2u(__floats2half2_rn(v0.z, v0.w));
        dst[2 * i] = o;
        o.x = h2u(__floats2half2_rn(v1.x, v1.y));
        o.y = h2u(__floats2half2_rn(v1.z, v1.w));
        dst[2 * i + 1] = o;
    }
}

// 8 half2 LDGs: A fragments for one k16 chunk over the 2 m16 tiles (32 rows).
__device__ __forceinline__ void loadA8(uint32_t a[8], const __half* __restrict__ p0,
                                       int rs) {
    #pragma unroll
    for (int mt = 0; mt < 2; ++mt) {
        const __half* p = p0 + (size_t)mt * 16 * rs;
        a[mt * 4 + 0] = __ldcg((const uint32_t*)(p));
        a[mt * 4 + 1] = __ldcg((const uint32_t*)(p + 8 * rs));
        a[mt * 4 + 2] = __ldcg((const uint32_t*)(p + 8));
        a[mt * 4 + 3] = __ldcg((const uint32_t*)(p + 8 * rs + 8));
    }
}

__device__ __forceinline__ void mma8(float acc[2][4][4], const uint32_t a[8],
                                     const uint32_t Bj[4][2]) {
    #pragma unroll
    for (int mt = 0; mt < 2; ++mt)
        #pragma unroll
        for (int nt = 0; nt < 4; ++nt)
            mma_f16(acc[mt][nt], a[mt*4+0], a[mt*4+1], a[mt*4+2], a[mt*4+3],
                    Bj[nt][0], Bj[nt][1]);
}

__global__ void __launch_bounds__(NTH, 1)
lstm_kernel(const float* __restrict__ W_ih,
            const float* __restrict__ W_hh,
            const float* __restrict__ b_ih,
            const float* __restrict__ b_hh)
{
    extern __shared__ float4 RB[];   // [8 warps][8 tiles][32 lanes] partial C frags (16KB)

    const int tid  = threadIdx.x;
    const int bid  = blockIdx.x;
    const int w    = tid >> 5;
    const int lane = tid & 31;
    const int gid  = lane >> 2;
    const int tig  = lane & 3;

    const int mg = bid & 1;          // m-group: batch rows mg*32 .. mg*32+31
    const int ng = bid >> 1;         // n-group: h cols ng*8 .. ng*8+7
    const int m0 = mg * 32;
    const int myctr = (bid >> 4) * CSTRIDE;   // this block's arrival counter slot

    // ---- one-time: gather B fragments (fp16) into registers ---------------
    uint32_t Bv[6][4][2];
    #pragma unroll
    for (int j = 0; j < 6; ++j) {
        const int C  = (j < 4) ? (w * 4 + j) : (32 + w * 2 + (j - 4));
        const int k0 = C * 16 + 2 * tig;
        #pragma unroll
        for (int nt = 0; nt < 4; ++nt) {
            int nl   = nt * 8 + gid;
            int grow = (nl & 3) * HDIM + ng * NHC + (nl >> 2);
            float v0, v1, v2, v3;
            if (C < 32) {
                const float* p = W_hh + (size_t)grow * HDIM + k0;
                v0 = p[0]; v1 = p[1]; v2 = p[8]; v3 = p[9];
            } else {
                const float* p = W_ih + (size_t)grow * IDIM + (k0 - HDIM);
                v0 = p[0]; v1 = p[1]; v2 = p[8]; v3 = p[9];
            }
            Bv[j][nt][0] = h2u(__floats2half2_rn(v0, v1));
            Bv[j][nt][1] = h2u(__floats2half2_rn(v2, v3));
        }
    }

    // ---- cell ownership: this thread finalizes 1 LSTM cell ----------------
    const int jj  = (w & 3) * 2 + (tig >> 1);
    const int col = ng * NHC + jj;
    const float bI = b_ih[0*HDIM + col] + b_hh[0*HDIM + col];
    const float bF = b_ih[1*HDIM + col] + b_hh[1*HDIM + col];
    const float bG = b_ih[2*HDIM + col] + b_hh[2*HDIM + col];
    const float bO = b_ih[3*HDIM + col] + b_hh[3*HDIM + col];
    float creg = 0.f;

    // invariant x base: row m0+gid, col = w*32 + 2*tig
    const __half* xp0 = &g_x[0][0][0] + (size_t)(m0 + gid) * TSTEPS * IDIM
                        + w * 32 + 2 * tig;

    // preload x A-fragments for t=0
    uint32_t xA0[8], xA1[8];
    loadA8(xA0, xp0,      TSTEPS * IDIM);
    loadA8(xA1, xp0 + 16, TSTEPS * IDIM);

    for (int t = 0; t < TSTEPS; ++t) {
        float acc[2][4][4];
        #pragma unroll
        for (int mt = 0; mt < 2; ++mt)
            #pragma unroll
            for (int nt = 0; nt < 4; ++nt)
                #pragma unroll
                for (int e = 0; e < 4; ++e) acc[mt][nt][e] = 0.f;

        // ---------- x phase: pure register mma, overlaps barrier wait ------
        mma8(acc, xA0, Bv[4]);
        mma8(acc, xA1, Bv[5]);

        // ---------- wait for h_t (8 concurrent pollers, one per counter) ---
        if (t > 0) {
            if (tid < NCTR) {
                volatile unsigned int* p = &g_bar[t - 1][tid * CSTRIDE];
                while (*p < (unsigned)ARRV) { }
            }
            __syncthreads();
        }

        // ---------- h phase (4 chunks, double-buffered) ----------
        {
            const __half* hb = &g_h[t & 1][0][0] + (size_t)(m0 + gid) * HDIM
                               + w * 64 + 2 * tig;
            uint32_t A0[8], A1[8];
            loadA8(A0, hb, HDIM);
            #pragma unroll
            for (int j = 0; j < 4; ++j) {
                if (j < 3) loadA8((j & 1) ? A0 : A1, hb + (j + 1) * 16, HDIM);
                mma8(acc, (j & 1) ? A1 : A0, Bv[j]);
            }
        }

        // ---------- prefetch x for t+1 (latency hidden behind epilogue) ----
        if (t + 1 < TSTEPS) {
            const __half* xb = xp0 + (size_t)(t + 1) * IDIM;
            loadA8(xA0, xb,      TSTEPS * IDIM);
            loadA8(xA1, xb + 16, TSTEPS * IDIM);
        }

        // ---------- cross-warp k-reduction in fragment space ----------
        #pragma unroll
        for (int mt = 0; mt < 2; ++mt)
            #pragma unroll
            for (int nt = 0; nt < 4; ++nt)
                RB[(w * 8 + mt * 4 + nt) * 32 + lane] =
                    make_float4(acc[mt][nt][0], acc[mt][nt][1], acc[mt][nt][2], acc[mt][nt][3]);
        __syncthreads();

        __half* __restrict__ hnext = &g_h[(t + 1) & 1][0][0];
        const bool odd = (tig & 1);

        {
            // warp w reduces slot s = w across the 8 warps
            float4 F = RB[(0 * 8 + w) * 32 + lane];
            #pragma unroll
            for (int ws = 1; ws < 8; ++ws) {
                float4 T = RB[(ws * 8 + w) * 32 + lane];
                F.x += T.x; F.y += T.y; F.z += T.z; F.w += T.w;
            }
            // exchange gate pairs: even lane ends with cell row gid, odd with gid+8
            float sx = odd ? F.x : F.z;
            float sy = odd ? F.y : F.w;
            float rx = __shfl_xor_sync(0xffffffffu, sx, 1);
            float ry = __shfl_xor_sync(0xffffffffu, sy, 1);
            float gi = odd ? rx : F.x;
            float gf = odd ? ry : F.y;
            float gg = odd ? F.z : rx;
            float go = odd ? F.w : ry;

            gi = sigf(gi + bI);
            gf = sigf(gf + bF);
            go = sigf(go + bO);
            gg = tanhff(gg + bG);
            float c = gf * creg + gi * gg;
            creg = c;
            float hv = go * tanhff(c);

            const int mt = w >> 2;
            const int b  = m0 + mt * 16 + gid + (odd ? 8 : 0);
            hnext[b * HDIM + col] = __float2half(hv);
        }

        // ---------- release h_{t+1} (hierarchical arrival) ----------
        __threadfence();
        __syncthreads();
        if (tid == 0) atomicAdd(&g_bar[t][myctr], 1u);
    }
}

__global__ void fc_kernel(const float* __restrict__ W_fc,
                          const float* __restrict__ b_fc,
                          float* __restrict__ out)
{
    int b    = blockIdx.x;
    int warp = threadIdx.x >> 5;
    int lane = threadIdx.x & 31;
    if (warp >= ODIM) return;
    const __half* h = &g_h[0][b][0];   // T even -> final h in buffer 0
    float acc = 0.f;
    for (int k = lane; k < HDIM; k += 32)
        acc += __half2float(h[k]) * W_fc[warp * HDIM + k];
    #pragma unroll
    for (int off = 16; off; off >>= 1)
        acc += __shfl_xor_sync(0xffffffffu, acc, off);
    if (lane == 0) out[b * ODIM + warp] = acc + b_fc[warp];
}

extern "C" void kernel_launch(void* const* d_in, const int* in_sizes, int n_in,
                              void* d_out, int out_size)
{
    const float* x    = (const float*)d_in[0];
    const float* W_ih = (const float*)d_in[1];
    const float* W_hh = (const float*)d_in[2];
    const float* b_ih = (const float*)d_in[3];
    const float* b_hh = (const float*)d_in[4];
    const float* W_fc = (const float*)d_in[5];
    const float* b_fc = (const float*)d_in[6];
    float* out = (float*)d_out;

    const int SMEM = 8 * 8 * 32 * (int)sizeof(float4);   // 16 KB
    cudaFuncSetAttribute(lstm_kernel,
                         cudaFuncAttributeMaxDynamicSharedMemorySize, SMEM);

    init_kernel<<<512, 256>>>();
    convert_x_kernel<<<2048, 256>>>(x);
    lstm_kernel<<<GB, NTH, SMEM>>>(W_ih, W_hh, b_ih, b_hh);
    fc_kernel<<<BATCH, 320>>>(W_fc, b_fc, out);
}